// round 11
// baseline (speedup 1.0000x reference)
#include <cuda_runtime.h>
#include <cstdint>

// ---------------------------------------------------------------------------
// ShiftWindowMSA (Swin-V2): B=8, H=W=128, C=256, heads=8, hd=32, ws=8, ss=4
// Round 8: pre-converted tf32 operands + cp.async 3-stage GEMM pipelines,
// attention with 2 threads/query-row (shfl-combined dots) for occupancy.
// ---------------------------------------------------------------------------

constexpr int CC    = 256;
constexpr int HEADS = 8;
constexpr int HD    = 32;
constexpr int SH    = 4;
constexpr int NTOK  = 64;
constexpr int BWIN  = 2048;

constexpr int A_WORDS = 128 * 36;              // 4608
constexpr int B_WORDS = 64 * 36;               // 2304
constexpr int STAGE_WORDS = A_WORDS + B_WORDS; // 6912
constexpr int QKV_SMEM_BYTES  = (3 * STAGE_WORDS + 128) * 4;  // + rowOff
constexpr int PROJ_SMEM_BYTES = (3 * STAGE_WORDS) * 4;

__device__ float    g_q[BWIN * HEADS * NTOK * HD];
__device__ float    g_k[BWIN * HEADS * NTOK * HD];
__device__ float    g_v[BWIN * HEADS * NTOK * HD];
__device__ uint32_t g_ao[BWIN * NTOK * CC];      // tf32 bits
__device__ uint32_t g_xt[8 * 16384 * 256];       // x as tf32 bits
__device__ uint32_t g_wq[768 * 256];             // qkv_w as tf32 bits
__device__ uint32_t g_wp[256 * 256];             // proj_w as tf32 bits
__device__ float    g_bt[225 * 8];
__device__ float    g_bias[HEADS * NTOK * NTOK]; // [h][m(key)][n(query)]

// ---------------------------------------------------------------------------
__device__ __forceinline__ uint32_t f2tf32(float f) {
    uint32_t r;
    asm("cvt.rna.tf32.f32 %0, %1;" : "=r"(r) : "f"(f));
    return r;
}
__device__ __forceinline__ uint4 cvt4(float4 f) {
    uint4 u;
    u.x = f2tf32(f.x); u.y = f2tf32(f.y); u.z = f2tf32(f.z); u.w = f2tf32(f.w);
    return u;
}
__device__ __forceinline__ void mma_tf32(float* d, const uint32_t* a,
                                         const uint32_t* b, const float* c) {
    asm("mma.sync.aligned.m16n8k8.row.col.f32.tf32.tf32.f32 "
        "{%0,%1,%2,%3}, {%4,%5,%6,%7}, {%8,%9}, {%10,%11,%12,%13};"
        : "=f"(d[0]), "=f"(d[1]), "=f"(d[2]), "=f"(d[3])
        : "r"(a[0]), "r"(a[1]), "r"(a[2]), "r"(a[3]),
          "r"(b[0]), "r"(b[1]),
          "f"(c[0]), "f"(c[1]), "f"(c[2]), "f"(c[3]));
}
__device__ __forceinline__ void cp16(uint32_t s, const void* g) {
    asm volatile("cp.async.cg.shared.global [%0], [%1], 16;" :: "r"(s), "l"(g));
}
__device__ __forceinline__ void cp_commit() {
    asm volatile("cp.async.commit_group;" ::: "memory");
}

// ---------------------------------------------------------------------------
// tf32 pre-conversion
// ---------------------------------------------------------------------------
__global__ void conv_tf32(const float4* __restrict__ s, uint4* __restrict__ d, int n4) {
    int i = blockIdx.x * blockDim.x + threadIdx.x;
    if (i < n4) d[i] = cvt4(s[i]);
}

// ---------------------------------------------------------------------------
// CPB MLP
// ---------------------------------------------------------------------------
__device__ __forceinline__ float cpb_coord(int i) {
    float c = (float)(i - 7) * (8.0f / 7.0f);
    float a = log2f(fabsf(c) + 1.0f) * (1.0f / 3.0f);
    return (c < 0.0f) ? -a : a;
}

__global__ void cpb_stage1(const float* __restrict__ w1, const float* __restrict__ b1,
                           const float* __restrict__ w2) {
    int idx = blockIdx.x * blockDim.x + threadIdx.x;
    if (idx >= 225 * 8) return;
    int t = idx >> 3, h = idx & 7;
    float t0 = cpb_coord(t / 15);
    float t1 = cpb_coord(t % 15);
    const float* w2h = w2 + h * 512;
    float acc = 0.0f;
    for (int o = 0; o < 512; o++) {
        float hid = fmaxf(fmaf(t0, w1[2 * o], fmaf(t1, w1[2 * o + 1], b1[o])), 0.0f);
        acc = fmaf(hid, w2h[o], acc);
    }
    g_bt[idx] = acc;
}

__global__ void cpb_stage2() {
    int idx = blockIdx.x * blockDim.x + threadIdx.x;
    int h = idx >> 12, rest = idx & 4095, m = rest >> 6, n = rest & 63;
    int dy = (n >> 3) - (m >> 3) + 7;
    int dx = (n & 7) - (m & 7) + 7;
    float b = g_bt[(dy * 15 + dx) * 8 + h];
    g_bias[idx] = 16.0f / (1.0f + __expf(-b));
}

// ---------------------------------------------------------------------------
// QKV GEMM (tf32, cp.async 3-stage): M=131072 gathered, N=768, K=256.
// 128x64 tile, BK=32. grid = (12, 1024), block = 256.
// ---------------------------------------------------------------------------
__global__ __launch_bounds__(256) void qkv_gemm_tc(
    const float* __restrict__ qb, const float* __restrict__ vb) {
    extern __shared__ uint32_t dyn[];
    int* rowOff = (int*)(dyn + 3 * STAGE_WORDS);
    const uint32_t smem_u32 = (uint32_t)__cvta_generic_to_shared(dyn);

    const int tid = threadIdx.x;
    const int mb  = blockIdx.y;
    const int jt  = blockIdx.x;

    if (tid < 128) {
        int gm = (mb << 7) + tid;
        int win = gm >> 6, n = gm & 63;
        int b = win >> 8, wloc = win & 255, wy = wloc >> 4, wx = wloc & 15;
        int ly = n >> 3, lx = n & 7;
        int hs  = ((wy << 3) + ly + SH) & 127;
        int ws_ = ((wx << 3) + lx + SH) & 127;
        rowOff[tid] = ((((b << 7) + hs) << 7) | ws_) << 8;
    }
    __syncthreads();

    const int lane  = tid & 31, warp = tid >> 5;
    const int warpM = warp & 3, warpN = warp >> 2;
    const int la_row = tid >> 1;           // 0..127
    const int la_seg = (tid & 1) << 4;     // 0 / 16
    const int lb_row = tid >> 2;           // 0..63 (n)
    const int lb_seg = (tid & 3) << 3;     // 0,8,16,24 (k)
    const uint32_t* xRow = g_xt + rowOff[la_row] + la_seg;
    const uint32_t* wRow = g_wq + ((jt << 6) + lb_row) * 256 + lb_seg;

    float acc[2][4][4] = {};

    auto issue = [&](int st) {
        int buf = st % 3;
        uint32_t A = smem_u32 + (buf * STAGE_WORDS) * 4;
        uint32_t Bb = A + A_WORDS * 4;
        int k0 = st << 5;
#pragma unroll
        for (int v = 0; v < 4; v++)
            cp16(A + (la_row * 36 + la_seg + v * 4) * 4, xRow + k0 + v * 4);
        cp16(Bb + (lb_row * 36 + lb_seg) * 4,     wRow + k0);
        cp16(Bb + (lb_row * 36 + lb_seg + 4) * 4, wRow + k0 + 4);
        cp_commit();
    };
    auto compute = [&](int buf) {
        const uint32_t* A = dyn + buf * STAGE_WORDS;
        const uint32_t* B = A + A_WORDS;
#pragma unroll
        for (int ksb = 0; ksb < 4; ksb++) {
            uint32_t a[2][4], b[4][2];
            const int kc = (ksb << 3) + (lane & 3);
#pragma unroll
            for (int mf = 0; mf < 2; mf++) {
                int r = (warpM << 5) + (mf << 4) + (lane >> 2);
                a[mf][0] = A[r * 36 + kc];       a[mf][1] = A[(r + 8) * 36 + kc];
                a[mf][2] = A[r * 36 + kc + 4];   a[mf][3] = A[(r + 8) * 36 + kc + 4];
            }
#pragma unroll
            for (int nf = 0; nf < 4; nf++) {
                int n = (warpN << 5) + (nf << 3) + (lane >> 2);
                b[nf][0] = B[n * 36 + kc];
                b[nf][1] = B[n * 36 + kc + 4];
            }
#pragma unroll
            for (int mf = 0; mf < 2; mf++)
#pragma unroll
                for (int nf = 0; nf < 4; nf++)
                    mma_tf32(acc[mf][nf], a[mf], b[nf], acc[mf][nf]);
        }
    };

    issue(0);
    issue(1);
#pragma unroll
    for (int it = 0; it < 8; it++) {
        if (it < 7) asm volatile("cp.async.wait_group 1;" ::: "memory");
        else        asm volatile("cp.async.wait_group 0;" ::: "memory");
        __syncthreads();
        if (it < 6) issue(it + 2);
        compute(it % 3);
    }

    const int sel = jt >> 2;   // 0:q 1:k 2:v
    float* dstBase = (sel == 0) ? g_q : ((sel == 1) ? g_k : g_v);
#pragma unroll
    for (int nf = 0; nf < 4; nf++) {
        int jg = (jt << 6) + (warpN << 5) + (nf << 3) + ((lane & 3) << 1);
        float2 bias = make_float2(0.0f, 0.0f);
        if (sel == 0)      bias = make_float2(qb[jg], qb[jg + 1]);
        else if (sel == 2) bias = make_float2(vb[jg - 512], vb[jg - 511]);
        int head = (jg >> 5) & 7, d = jg & 31;
#pragma unroll
        for (int mf = 0; mf < 2; mf++) {
#pragma unroll
            for (int half = 0; half < 2; half++) {
                int r  = (warpM << 5) + (mf << 4) + (lane >> 2) + half * 8;
                int gm = (mb << 7) + r;
                int win = gm >> 6, n = gm & 63;
                float2 val = make_float2(acc[mf][nf][half * 2 + 0] + bias.x,
                                         acc[mf][nf][half * 2 + 1] + bias.y);
                float* dst = dstBase + ((size_t)(((win << 3) + head) << 6 | n) << 5) + d;
                *reinterpret_cast<float2*>(dst) = val;
            }
        }
    }
}

// ---------------------------------------------------------------------------
// Attention: one (win,head) pair per 128-thread block; 2 threads per query
// row (d-halves combined via shfl_xor(1)). K+V in smem (18.4 KB), single-pass
// softmax (mx = scale+16 bound), bitmask shift mask, tf32 output into g_ao.
// grid = 16384, block = 128.
// ---------------------------------------------------------------------------
__device__ __forceinline__ int region9(int wy, int wx, int n) {
    int rh = (wy == 15) ? (((n >> 3) < 4) ? 1 : 2) : 0;
    int rw = (wx == 15) ? (((n & 7) < 4) ? 1 : 2) : 0;
    return rh * 3 + rw;
}

__global__ __launch_bounds__(128) void attn_kernel(const float* __restrict__ ls) {
    __shared__ float ks[64][36];
    __shared__ float vs[64][36];
    const int tid  = threadIdx.x;
    const int row  = tid >> 1;       // query / K row 0..63
    const int hb   = (tid & 1) << 4; // d-half base: 0 or 16
    const int pair = blockIdx.x;
    const int win  = pair >> 3, h = pair & 7;

    // stage K and V
    {
        const float4* kp = reinterpret_cast<const float4*>(
            g_k + (size_t)pair * (NTOK * HD));
        const float4* vp = reinterpret_cast<const float4*>(
            g_v + (size_t)pair * (NTOK * HD));
#pragma unroll
        for (int i = tid; i < NTOK * HD / 4; i += 128) {
            *reinterpret_cast<float4*>(&ks[i >> 3][(i & 7) << 2]) = kp[i];
            *reinterpret_cast<float4*>(&vs[i >> 3][(i & 7) << 2]) = vp[i];
        }
    }
    __syncthreads();

    // normalize own K row-half (combine norms across the 2 half-threads)
    {
        float4 k0 = *reinterpret_cast<float4*>(&ks[row][hb]);
        float4 k1 = *reinterpret_cast<float4*>(&ks[row][hb + 4]);
        float4 k2 = *reinterpret_cast<float4*>(&ks[row][hb + 8]);
        float4 k3 = *reinterpret_cast<float4*>(&ks[row][hb + 12]);
        float s0 = fmaf(k0.x, k0.x, fmaf(k0.y, k0.y, fmaf(k0.z, k0.z, k0.w * k0.w)));
        float s1 = fmaf(k1.x, k1.x, fmaf(k1.y, k1.y, fmaf(k1.z, k1.z, k1.w * k1.w)));
        float s2 = fmaf(k2.x, k2.x, fmaf(k2.y, k2.y, fmaf(k2.z, k2.z, k2.w * k2.w)));
        float s3 = fmaf(k3.x, k3.x, fmaf(k3.y, k3.y, fmaf(k3.z, k3.z, k3.w * k3.w)));
        float s = (s0 + s1) + (s2 + s3);
        s += __shfl_xor_sync(0xffffffffu, s, 1);
        float inv = rsqrtf(fmaxf(s, 1e-24f));
        k0.x *= inv; k0.y *= inv; k0.z *= inv; k0.w *= inv;
        k1.x *= inv; k1.y *= inv; k1.z *= inv; k1.w *= inv;
        k2.x *= inv; k2.y *= inv; k2.z *= inv; k2.w *= inv;
        k3.x *= inv; k3.y *= inv; k3.z *= inv; k3.w *= inv;
        *reinterpret_cast<float4*>(&ks[row][hb])      = k0;
        *reinterpret_cast<float4*>(&ks[row][hb + 4])  = k1;
        *reinterpret_cast<float4*>(&ks[row][hb + 8])  = k2;
        *reinterpret_cast<float4*>(&ks[row][hb + 12]) = k3;
    }

    // own Q row-half, normalized and pre-scaled
    float q[16];
    float scale = __expf(fminf(ls[h], 4.6051702f));
    {
        const float4* qp = reinterpret_cast<const float4*>(
            g_q + ((size_t)pair * NTOK + row) * HD + hb);
        float s0 = 0.0f, s1 = 0.0f, s2 = 0.0f, s3 = 0.0f;
#pragma unroll
        for (int d4 = 0; d4 < 4; d4++) {
            float4 f = qp[d4];
            q[d4 * 4 + 0] = f.x; q[d4 * 4 + 1] = f.y;
            q[d4 * 4 + 2] = f.z; q[d4 * 4 + 3] = f.w;
            s0 = fmaf(f.x, f.x, s0); s1 = fmaf(f.y, f.y, s1);
            s2 = fmaf(f.z, f.z, s2); s3 = fmaf(f.w, f.w, s3);
        }
        float s = (s0 + s1) + (s2 + s3);
        s += __shfl_xor_sync(0xffffffffu, s, 1);
        float inv = rsqrtf(fmaxf(s, 1e-24f)) * scale;
#pragma unroll
        for (int d = 0; d < 16; d++) q[d] *= inv;
    }
    __syncthreads();

    // shift mask bitmask (nonzero only for boundary windows)
    const int wloc = win & 255, wy = wloc >> 4, wx = wloc & 15;
    uint32_t mlo = 0, mhi = 0;
    if (wy == 15 || wx == 15) {
        const int rn = region9(wy, wx, row);
        for (int m = 0; m < 64; m++)
            if (region9(wy, wx, m) != rn) {
                if (m < 32) mlo |= (1u << m); else mhi |= (1u << (m - 32));
            }
    }

    const float* biasT = g_bias + (h << 12) + row;   // [h][m][n]: +64 per m
    const float mx = scale + 16.0f;

    float sum = 0.0f;
    float out[16] = {};
#pragma unroll 4
    for (int m = 0; m < 64; m++) {
        float4 k0 = *reinterpret_cast<const float4*>(&ks[m][hb]);
        float4 k1 = *reinterpret_cast<const float4*>(&ks[m][hb + 4]);
        float4 k2 = *reinterpret_cast<const float4*>(&ks[m][hb + 8]);
        float4 k3 = *reinterpret_cast<const float4*>(&ks[m][hb + 12]);
        float a0 = fmaf(q[0], k0.x, fmaf(q[4],  k1.x, fmaf(q[8],  k2.x, q[12] * k3.x)));
        float a1 = fmaf(q[1], k0.y, fmaf(q[5],  k1.y, fmaf(q[9],  k2.y, q[13] * k3.y)));
        float a2 = fmaf(q[2], k0.z, fmaf(q[6],  k1.z, fmaf(q[10], k2.z, q[14] * k3.z)));
        float a3 = fmaf(q[3], k0.w, fmaf(q[7],  k1.w, fmaf(q[11], k2.w, q[15] * k3.w)));
        float half_dot = (a0 + a1) + (a2 + a3);
        float dot = half_dot + __shfl_xor_sync(0xffffffffu, half_dot, 1);
        uint32_t bit = (m < 32) ? ((mlo >> m) & 1u) : ((mhi >> (m - 32)) & 1u);
        float v = dot + __ldg(&biasT[m << 6]) + (bit ? -100.0f : 0.0f);
        float e = __expf(v - mx);
        sum += e;
        float4 v0 = *reinterpret_cast<const float4*>(&vs[m][hb]);
        float4 v1 = *reinterpret_cast<const float4*>(&vs[m][hb + 4]);
        float4 v2 = *reinterpret_cast<const float4*>(&vs[m][hb + 8]);
        float4 v3 = *reinterpret_cast<const float4*>(&vs[m][hb + 12]);
        out[0]  = fmaf(e, v0.x, out[0]);  out[1]  = fmaf(e, v0.y, out[1]);
        out[2]  = fmaf(e, v0.z, out[2]);  out[3]  = fmaf(e, v0.w, out[3]);
        out[4]  = fmaf(e, v1.x, out[4]);  out[5]  = fmaf(e, v1.y, out[5]);
        out[6]  = fmaf(e, v1.z, out[6]);  out[7]  = fmaf(e, v1.w, out[7]);
        out[8]  = fmaf(e, v2.x, out[8]);  out[9]  = fmaf(e, v2.y, out[9]);
        out[10] = fmaf(e, v2.z, out[10]); out[11] = fmaf(e, v2.w, out[11]);
        out[12] = fmaf(e, v3.x, out[12]); out[13] = fmaf(e, v3.y, out[13]);
        out[14] = fmaf(e, v3.z, out[14]); out[15] = fmaf(e, v3.w, out[15]);
    }
    float rinv = 1.0f / sum;

    uint32_t* op = g_ao + ((size_t)(win << 6) + row) * CC + (h << 5) + hb;
#pragma unroll
    for (int d = 0; d < 16; d += 4) {
        uint4 u;
        u.x = f2tf32(out[d] * rinv);     u.y = f2tf32(out[d + 1] * rinv);
        u.z = f2tf32(out[d + 2] * rinv); u.w = f2tf32(out[d + 3] * rinv);
        *reinterpret_cast<uint4*>(op + d) = u;
    }
}

// ---------------------------------------------------------------------------
// Projection GEMM (tf32, cp.async 3-stage): M=131072, N=256, K=256; fused
// window-reverse + unshift scatter. grid = (4, 1024), block = 256.
// ---------------------------------------------------------------------------
__global__ __launch_bounds__(256) void proj_gemm_tc(
    const float* __restrict__ pb, float* __restrict__ out) {
    extern __shared__ uint32_t dyn[];
    const uint32_t smem_u32 = (uint32_t)__cvta_generic_to_shared(dyn);

    const int tid = threadIdx.x;
    const int mb  = blockIdx.y;
    const int jt  = blockIdx.x;

    const int lane  = tid & 31, warp = tid >> 5;
    const int warpM = warp & 3, warpN = warp >> 2;
    const int la_row = tid >> 1;
    const int la_seg = (tid & 1) << 4;
    const int lb_row = tid >> 2;
    const int lb_seg = (tid & 3) << 3;
    const uint32_t* aRow = g_ao + (size_t)((mb << 7) + la_row) * 256 + la_seg;
    const uint32_t* wRow = g_wp + ((jt << 6) + lb_row) * 256 + lb_seg;

    float acc[2][4][4] = {};

    auto issue = [&](int st) {
        int buf = st % 3;
        uint32_t A = smem_u32 + (buf * STAGE_WORDS) * 4;
        uint32_t Bb = A + A_WORDS * 4;
        int k0 = st << 5;
#pragma unroll
        for (int v = 0; v < 4; v++)
            cp16(A + (la_row * 36 + la_seg + v * 4) * 4, aRow + k0 + v * 4);
        cp16(Bb + (lb_row * 36 + lb_seg) * 4,     wRow + k0);
        cp16(Bb + (lb_row * 36 + lb_seg + 4) * 4, wRow + k0 + 4);
        cp_commit();
    };
    auto compute = [&](int buf) {
        const uint32_t* A = dyn + buf * STAGE_WORDS;
        const uint32_t* B = A + A_WORDS;
#pragma unroll
        for (int ksb = 0; ksb < 4; ksb++) {
            uint32_t a[2][4], b[4][2];
            const int kc = (ksb << 3) + (lane & 3);
#pragma unroll
            for (int mf = 0; mf < 2; mf++) {
                int r = (warpM << 5) + (mf << 4) + (lane >> 2);
                a[mf][0] = A[r * 36 + kc];       a[mf][1] = A[(r + 8) * 36 + kc];
                a[mf][2] = A[r * 36 + kc + 4];   a[mf][3] = A[(r + 8) * 36 + kc + 4];
            }
#pragma unroll
            for (int nf = 0; nf < 4; nf++) {
                int n = (warpN << 5) + (nf << 3) + (lane >> 2);
                b[nf][0] = B[n * 36 + kc];
                b[nf][1] = B[n * 36 + kc + 4];
            }
#pragma unroll
            for (int mf = 0; mf < 2; mf++)
#pragma unroll
                for (int nf = 0; nf < 4; nf++)
                    mma_tf32(acc[mf][nf], a[mf], b[nf], acc[mf][nf]);
        }
    };

    issue(0);
    issue(1);
#pragma unroll
    for (int it = 0; it < 8; it++) {
        if (it < 7) asm volatile("cp.async.wait_group 1;" ::: "memory");
        else        asm volatile("cp.async.wait_group 0;" ::: "memory");
        __syncthreads();
        if (it < 6) issue(it + 2);
        compute(it % 3);
    }

#pragma unroll
    for (int nf = 0; nf < 4; nf++) {
        int jg = (jt << 6) + (warpN << 5) + (nf << 3) + ((lane & 3) << 1);
        float2 bias = make_float2(pb[jg], pb[jg + 1]);
#pragma unroll
        for (int mf = 0; mf < 2; mf++) {
#pragma unroll
            for (int half = 0; half < 2; half++) {
                int r  = (warpM << 5) + (mf << 4) + (lane >> 2) + half * 8;
                int gm = (mb << 7) + r;
                int win = gm >> 6, n = gm & 63;
                int b = win >> 8, wloc = win & 255, wy = wloc >> 4, wx = wloc & 15;
                int ly = n >> 3, lx = n & 7;
                int hd_ = ((wy << 3) + ly + SH) & 127;
                int wd_ = ((wx << 3) + lx + SH) & 127;
                size_t rowoff = ((size_t)((((b << 7) + hd_) << 7) | wd_)) << 8;
                float2 val = make_float2(acc[mf][nf][half * 2 + 0] + bias.x,
                                         acc[mf][nf][half * 2 + 1] + bias.y);
                *reinterpret_cast<float2*>(out + rowoff + jg) = val;
            }
        }
    }
}

// ---------------------------------------------------------------------------
extern "C" void kernel_launch(void* const* d_in, const int* in_sizes, int n_in,
                              void* d_out, int out_size) {
    const float* x      = (const float*)d_in[0];
    const float* qkv_w  = (const float*)d_in[1];
    const float* q_bias = (const float*)d_in[2];
    const float* v_bias = (const float*)d_in[3];
    const float* lscale = (const float*)d_in[4];
    const float* cpb_w1 = (const float*)d_in[5];
    const float* cpb_b1 = (const float*)d_in[6];
    const float* cpb_w2 = (const float*)d_in[7];
    const float* proj_w = (const float*)d_in[8];
    const float* proj_b = (const float*)d_in[9];
    float* out = (float*)d_out;

    cudaFuncSetAttribute(qkv_gemm_tc, cudaFuncAttributeMaxDynamicSharedMemorySize,
                         QKV_SMEM_BYTES);
    cudaFuncSetAttribute(proj_gemm_tc, cudaFuncAttributeMaxDynamicSharedMemorySize,
                         PROJ_SMEM_BYTES);

    uint32_t* xt_dev;  cudaGetSymbolAddress((void**)&xt_dev, g_xt);
    uint32_t* wq_dev;  cudaGetSymbolAddress((void**)&wq_dev, g_wq);
    uint32_t* wp_dev;  cudaGetSymbolAddress((void**)&wp_dev, g_wp);

    // pre-convert operands to tf32 bits
    conv_tf32<<<32768, 256>>>((const float4*)x, (uint4*)xt_dev, 8 * 16384 * 256 / 4);
    conv_tf32<<<192, 256>>>((const float4*)qkv_w, (uint4*)wq_dev, 768 * 256 / 4);
    conv_tf32<<<64, 256>>>((const float4*)proj_w, (uint4*)wp_dev, 256 * 256 / 4);

    cpb_stage1<<<8, 256>>>(cpb_w1, cpb_b1, cpb_w2);
    cpb_stage2<<<128, 256>>>();
    qkv_gemm_tc<<<dim3(12, 1024), 256, QKV_SMEM_BYTES>>>(q_bias, v_bias);
    attn_kernel<<<16384, 128>>>(lscale);
    proj_gemm_tc<<<dim3(4, 1024), 256, PROJ_SMEM_BYTES>>>(proj_b, out);
}

// round 12
// speedup vs baseline: 1.0018x; 1.0018x over previous
#include <cuda_runtime.h>
#include <cstdint>

// ---------------------------------------------------------------------------
// ShiftWindowMSA (Swin-V2): B=8, H=W=128, C=256, heads=8, hd=32, ws=8, ss=4
// Round 8: pre-converted tf32 operands + cp.async 3-stage GEMM pipelines,
// attention with 2 threads/query-row (shfl-combined dots) for occupancy.
// ---------------------------------------------------------------------------

constexpr int CC    = 256;
constexpr int HEADS = 8;
constexpr int HD    = 32;
constexpr int SH    = 4;
constexpr int NTOK  = 64;
constexpr int BWIN  = 2048;

constexpr int A_WORDS = 128 * 36;              // 4608
constexpr int B_WORDS = 64 * 36;               // 2304
constexpr int STAGE_WORDS = A_WORDS + B_WORDS; // 6912
constexpr int QKV_SMEM_BYTES  = (3 * STAGE_WORDS + 128) * 4;  // + rowOff
constexpr int PROJ_SMEM_BYTES = (3 * STAGE_WORDS) * 4;

__device__ float    g_q[BWIN * HEADS * NTOK * HD];
__device__ float    g_k[BWIN * HEADS * NTOK * HD];
__device__ float    g_v[BWIN * HEADS * NTOK * HD];
__device__ uint32_t g_ao[BWIN * NTOK * CC];      // tf32 bits
__device__ uint32_t g_xt[8 * 16384 * 256];       // x as tf32 bits
__device__ uint32_t g_wq[768 * 256];             // qkv_w as tf32 bits
__device__ uint32_t g_wp[256 * 256];             // proj_w as tf32 bits
__device__ float    g_bt[225 * 8];
__device__ float    g_bias[HEADS * NTOK * NTOK]; // [h][m(key)][n(query)]

// ---------------------------------------------------------------------------
__device__ __forceinline__ uint32_t f2tf32(float f) {
    uint32_t r;
    asm("cvt.rna.tf32.f32 %0, %1;" : "=r"(r) : "f"(f));
    return r;
}
__device__ __forceinline__ uint4 cvt4(float4 f) {
    uint4 u;
    u.x = f2tf32(f.x); u.y = f2tf32(f.y); u.z = f2tf32(f.z); u.w = f2tf32(f.w);
    return u;
}
__device__ __forceinline__ void mma_tf32(float* d, const uint32_t* a,
                                         const uint32_t* b, const float* c) {
    asm("mma.sync.aligned.m16n8k8.row.col.f32.tf32.tf32.f32 "
        "{%0,%1,%2,%3}, {%4,%5,%6,%7}, {%8,%9}, {%10,%11,%12,%13};"
        : "=f"(d[0]), "=f"(d[1]), "=f"(d[2]), "=f"(d[3])
        : "r"(a[0]), "r"(a[1]), "r"(a[2]), "r"(a[3]),
          "r"(b[0]), "r"(b[1]),
          "f"(c[0]), "f"(c[1]), "f"(c[2]), "f"(c[3]));
}
__device__ __forceinline__ void cp16(uint32_t s, const void* g) {
    asm volatile("cp.async.cg.shared.global [%0], [%1], 16;" :: "r"(s), "l"(g));
}
__device__ __forceinline__ void cp_commit() {
    asm volatile("cp.async.commit_group;" ::: "memory");
}

// ---------------------------------------------------------------------------
// tf32 pre-conversion
// ---------------------------------------------------------------------------
__global__ void conv_tf32(const float4* __restrict__ s, uint4* __restrict__ d, int n4) {
    int i = blockIdx.x * blockDim.x + threadIdx.x;
    if (i < n4) d[i] = cvt4(s[i]);
}

// ---------------------------------------------------------------------------
// CPB MLP
// ---------------------------------------------------------------------------
__device__ __forceinline__ float cpb_coord(int i) {
    float c = (float)(i - 7) * (8.0f / 7.0f);
    float a = log2f(fabsf(c) + 1.0f) * (1.0f / 3.0f);
    return (c < 0.0f) ? -a : a;
}

__global__ void cpb_stage1(const float* __restrict__ w1, const float* __restrict__ b1,
                           const float* __restrict__ w2) {
    int idx = blockIdx.x * blockDim.x + threadIdx.x;
    if (idx >= 225 * 8) return;
    int t = idx >> 3, h = idx & 7;
    float t0 = cpb_coord(t / 15);
    float t1 = cpb_coord(t % 15);
    const float* w2h = w2 + h * 512;
    float acc = 0.0f;
    for (int o = 0; o < 512; o++) {
        float hid = fmaxf(fmaf(t0, w1[2 * o], fmaf(t1, w1[2 * o + 1], b1[o])), 0.0f);
        acc = fmaf(hid, w2h[o], acc);
    }
    g_bt[idx] = acc;
}

__global__ void cpb_stage2() {
    int idx = blockIdx.x * blockDim.x + threadIdx.x;
    int h = idx >> 12, rest = idx & 4095, m = rest >> 6, n = rest & 63;
    int dy = (n >> 3) - (m >> 3) + 7;
    int dx = (n & 7) - (m & 7) + 7;
    float b = g_bt[(dy * 15 + dx) * 8 + h];
    g_bias[idx] = 16.0f / (1.0f + __expf(-b));
}

// ---------------------------------------------------------------------------
// QKV GEMM (tf32, cp.async 3-stage): M=131072 gathered, N=768, K=256.
// 128x64 tile, BK=32. grid = (12, 1024), block = 256.
// ---------------------------------------------------------------------------
__global__ __launch_bounds__(256) void qkv_gemm_tc(
    const float* __restrict__ qb, const float* __restrict__ vb) {
    extern __shared__ uint32_t dyn[];
    int* rowOff = (int*)(dyn + 3 * STAGE_WORDS);
    const uint32_t smem_u32 = (uint32_t)__cvta_generic_to_shared(dyn);

    const int tid = threadIdx.x;
    const int mb  = blockIdx.y;
    const int jt  = blockIdx.x;

    if (tid < 128) {
        int gm = (mb << 7) + tid;
        int win = gm >> 6, n = gm & 63;
        int b = win >> 8, wloc = win & 255, wy = wloc >> 4, wx = wloc & 15;
        int ly = n >> 3, lx = n & 7;
        int hs  = ((wy << 3) + ly + SH) & 127;
        int ws_ = ((wx << 3) + lx + SH) & 127;
        rowOff[tid] = ((((b << 7) + hs) << 7) | ws_) << 8;
    }
    __syncthreads();

    const int lane  = tid & 31, warp = tid >> 5;
    const int warpM = warp & 3, warpN = warp >> 2;
    const int la_row = tid >> 1;           // 0..127
    const int la_seg = (tid & 1) << 4;     // 0 / 16
    const int lb_row = tid >> 2;           // 0..63 (n)
    const int lb_seg = (tid & 3) << 3;     // 0,8,16,24 (k)
    const uint32_t* xRow = g_xt + rowOff[la_row] + la_seg;
    const uint32_t* wRow = g_wq + ((jt << 6) + lb_row) * 256 + lb_seg;

    float acc[2][4][4] = {};

    auto issue = [&](int st) {
        int buf = st % 3;
        uint32_t A = smem_u32 + (buf * STAGE_WORDS) * 4;
        uint32_t Bb = A + A_WORDS * 4;
        int k0 = st << 5;
#pragma unroll
        for (int v = 0; v < 4; v++)
            cp16(A + (la_row * 36 + la_seg + v * 4) * 4, xRow + k0 + v * 4);
        cp16(Bb + (lb_row * 36 + lb_seg) * 4,     wRow + k0);
        cp16(Bb + (lb_row * 36 + lb_seg + 4) * 4, wRow + k0 + 4);
        cp_commit();
    };
    auto compute = [&](int buf) {
        const uint32_t* A = dyn + buf * STAGE_WORDS;
        const uint32_t* B = A + A_WORDS;
#pragma unroll
        for (int ksb = 0; ksb < 4; ksb++) {
            uint32_t a[2][4], b[4][2];
            const int kc = (ksb << 3) + (lane & 3);
#pragma unroll
            for (int mf = 0; mf < 2; mf++) {
                int r = (warpM << 5) + (mf << 4) + (lane >> 2);
                a[mf][0] = A[r * 36 + kc];       a[mf][1] = A[(r + 8) * 36 + kc];
                a[mf][2] = A[r * 36 + kc + 4];   a[mf][3] = A[(r + 8) * 36 + kc + 4];
            }
#pragma unroll
            for (int nf = 0; nf < 4; nf++) {
                int n = (warpN << 5) + (nf << 3) + (lane >> 2);
                b[nf][0] = B[n * 36 + kc];
                b[nf][1] = B[n * 36 + kc + 4];
            }
#pragma unroll
            for (int mf = 0; mf < 2; mf++)
#pragma unroll
                for (int nf = 0; nf < 4; nf++)
                    mma_tf32(acc[mf][nf], a[mf], b[nf], acc[mf][nf]);
        }
    };

    issue(0);
    issue(1);
#pragma unroll
    for (int it = 0; it < 8; it++) {
        if (it < 7) asm volatile("cp.async.wait_group 1;" ::: "memory");
        else        asm volatile("cp.async.wait_group 0;" ::: "memory");
        __syncthreads();
        if (it < 6) issue(it + 2);
        compute(it % 3);
    }

    const int sel = jt >> 2;   // 0:q 1:k 2:v
    float* dstBase = (sel == 0) ? g_q : ((sel == 1) ? g_k : g_v);
#pragma unroll
    for (int nf = 0; nf < 4; nf++) {
        int jg = (jt << 6) + (warpN << 5) + (nf << 3) + ((lane & 3) << 1);
        float2 bias = make_float2(0.0f, 0.0f);
        if (sel == 0)      bias = make_float2(qb[jg], qb[jg + 1]);
        else if (sel == 2) bias = make_float2(vb[jg - 512], vb[jg - 511]);
        int head = (jg >> 5) & 7, d = jg & 31;
#pragma unroll
        for (int mf = 0; mf < 2; mf++) {
#pragma unroll
            for (int half = 0; half < 2; half++) {
                int r  = (warpM << 5) + (mf << 4) + (lane >> 2) + half * 8;
                int gm = (mb << 7) + r;
                int win = gm >> 6, n = gm & 63;
                float2 val = make_float2(acc[mf][nf][half * 2 + 0] + bias.x,
                                         acc[mf][nf][half * 2 + 1] + bias.y);
                float* dst = dstBase + ((size_t)(((win << 3) + head) << 6 | n) << 5) + d;
                *reinterpret_cast<float2*>(dst) = val;
            }
        }
    }
}

// ---------------------------------------------------------------------------
// Attention: one (win,head) pair per 128-thread block; 2 threads per query
// row (d-halves combined via shfl_xor(1)). K+V in smem (18.4 KB), single-pass
// softmax (mx = scale+16 bound), bitmask shift mask, tf32 output into g_ao.
// grid = 16384, block = 128.
// ---------------------------------------------------------------------------
__device__ __forceinline__ int region9(int wy, int wx, int n) {
    int rh = (wy == 15) ? (((n >> 3) < 4) ? 1 : 2) : 0;
    int rw = (wx == 15) ? (((n & 7) < 4) ? 1 : 2) : 0;
    return rh * 3 + rw;
}

__global__ __launch_bounds__(128) void attn_kernel(const float* __restrict__ ls) {
    __shared__ float ks[64][36];
    __shared__ float vs[64][36];
    const int tid  = threadIdx.x;
    const int row  = tid >> 1;       // query / K row 0..63
    const int hb   = (tid & 1) << 4; // d-half base: 0 or 16
    const int pair = blockIdx.x;
    const int win  = pair >> 3, h = pair & 7;

    // stage K and V
    {
        const float4* kp = reinterpret_cast<const float4*>(
            g_k + (size_t)pair * (NTOK * HD));
        const float4* vp = reinterpret_cast<const float4*>(
            g_v + (size_t)pair * (NTOK * HD));
#pragma unroll
        for (int i = tid; i < NTOK * HD / 4; i += 128) {
            *reinterpret_cast<float4*>(&ks[i >> 3][(i & 7) << 2]) = kp[i];
            *reinterpret_cast<float4*>(&vs[i >> 3][(i & 7) << 2]) = vp[i];
        }
    }
    __syncthreads();

    // normalize own K row-half (combine norms across the 2 half-threads)
    {
        float4 k0 = *reinterpret_cast<float4*>(&ks[row][hb]);
        float4 k1 = *reinterpret_cast<float4*>(&ks[row][hb + 4]);
        float4 k2 = *reinterpret_cast<float4*>(&ks[row][hb + 8]);
        float4 k3 = *reinterpret_cast<float4*>(&ks[row][hb + 12]);
        float s0 = fmaf(k0.x, k0.x, fmaf(k0.y, k0.y, fmaf(k0.z, k0.z, k0.w * k0.w)));
        float s1 = fmaf(k1.x, k1.x, fmaf(k1.y, k1.y, fmaf(k1.z, k1.z, k1.w * k1.w)));
        float s2 = fmaf(k2.x, k2.x, fmaf(k2.y, k2.y, fmaf(k2.z, k2.z, k2.w * k2.w)));
        float s3 = fmaf(k3.x, k3.x, fmaf(k3.y, k3.y, fmaf(k3.z, k3.z, k3.w * k3.w)));
        float s = (s0 + s1) + (s2 + s3);
        s += __shfl_xor_sync(0xffffffffu, s, 1);
        float inv = rsqrtf(fmaxf(s, 1e-24f));
        k0.x *= inv; k0.y *= inv; k0.z *= inv; k0.w *= inv;
        k1.x *= inv; k1.y *= inv; k1.z *= inv; k1.w *= inv;
        k2.x *= inv; k2.y *= inv; k2.z *= inv; k2.w *= inv;
        k3.x *= inv; k3.y *= inv; k3.z *= inv; k3.w *= inv;
        *reinterpret_cast<float4*>(&ks[row][hb])      = k0;
        *reinterpret_cast<float4*>(&ks[row][hb + 4])  = k1;
        *reinterpret_cast<float4*>(&ks[row][hb + 8])  = k2;
        *reinterpret_cast<float4*>(&ks[row][hb + 12]) = k3;
    }

    // own Q row-half, normalized and pre-scaled
    float q[16];
    float scale = __expf(fminf(ls[h], 4.6051702f));
    {
        const float4* qp = reinterpret_cast<const float4*>(
            g_q + ((size_t)pair * NTOK + row) * HD + hb);
        float s0 = 0.0f, s1 = 0.0f, s2 = 0.0f, s3 = 0.0f;
#pragma unroll
        for (int d4 = 0; d4 < 4; d4++) {
            float4 f = qp[d4];
            q[d4 * 4 + 0] = f.x; q[d4 * 4 + 1] = f.y;
            q[d4 * 4 + 2] = f.z; q[d4 * 4 + 3] = f.w;
            s0 = fmaf(f.x, f.x, s0); s1 = fmaf(f.y, f.y, s1);
            s2 = fmaf(f.z, f.z, s2); s3 = fmaf(f.w, f.w, s3);
        }
        float s = (s0 + s1) + (s2 + s3);
        s += __shfl_xor_sync(0xffffffffu, s, 1);
        float inv = rsqrtf(fmaxf(s, 1e-24f)) * scale;
#pragma unroll
        for (int d = 0; d < 16; d++) q[d] *= inv;
    }
    __syncthreads();

    // shift mask bitmask (nonzero only for boundary windows)
    const int wloc = win & 255, wy = wloc >> 4, wx = wloc & 15;
    uint32_t mlo = 0, mhi = 0;
    if (wy == 15 || wx == 15) {
        const int rn = region9(wy, wx, row);
        for (int m = 0; m < 64; m++)
            if (region9(wy, wx, m) != rn) {
                if (m < 32) mlo |= (1u << m); else mhi |= (1u << (m - 32));
            }
    }

    const float* biasT = g_bias + (h << 12) + row;   // [h][m][n]: +64 per m
    const float mx = scale + 16.0f;

    float sum = 0.0f;
    float out[16] = {};
#pragma unroll 4
    for (int m = 0; m < 64; m++) {
        float4 k0 = *reinterpret_cast<const float4*>(&ks[m][hb]);
        float4 k1 = *reinterpret_cast<const float4*>(&ks[m][hb + 4]);
        float4 k2 = *reinterpret_cast<const float4*>(&ks[m][hb + 8]);
        float4 k3 = *reinterpret_cast<const float4*>(&ks[m][hb + 12]);
        float a0 = fmaf(q[0], k0.x, fmaf(q[4],  k1.x, fmaf(q[8],  k2.x, q[12] * k3.x)));
        float a1 = fmaf(q[1], k0.y, fmaf(q[5],  k1.y, fmaf(q[9],  k2.y, q[13] * k3.y)));
        float a2 = fmaf(q[2], k0.z, fmaf(q[6],  k1.z, fmaf(q[10], k2.z, q[14] * k3.z)));
        float a3 = fmaf(q[3], k0.w, fmaf(q[7],  k1.w, fmaf(q[11], k2.w, q[15] * k3.w)));
        float half_dot = (a0 + a1) + (a2 + a3);
        float dot = half_dot + __shfl_xor_sync(0xffffffffu, half_dot, 1);
        uint32_t bit = (m < 32) ? ((mlo >> m) & 1u) : ((mhi >> (m - 32)) & 1u);
        float v = dot + __ldg(&biasT[m << 6]) + (bit ? -100.0f : 0.0f);
        float e = __expf(v - mx);
        sum += e;
        float4 v0 = *reinterpret_cast<const float4*>(&vs[m][hb]);
        float4 v1 = *reinterpret_cast<const float4*>(&vs[m][hb + 4]);
        float4 v2 = *reinterpret_cast<const float4*>(&vs[m][hb + 8]);
        float4 v3 = *reinterpret_cast<const float4*>(&vs[m][hb + 12]);
        out[0]  = fmaf(e, v0.x, out[0]);  out[1]  = fmaf(e, v0.y, out[1]);
        out[2]  = fmaf(e, v0.z, out[2]);  out[3]  = fmaf(e, v0.w, out[3]);
        out[4]  = fmaf(e, v1.x, out[4]);  out[5]  = fmaf(e, v1.y, out[5]);
        out[6]  = fmaf(e, v1.z, out[6]);  out[7]  = fmaf(e, v1.w, out[7]);
        out[8]  = fmaf(e, v2.x, out[8]);  out[9]  = fmaf(e, v2.y, out[9]);
        out[10] = fmaf(e, v2.z, out[10]); out[11] = fmaf(e, v2.w, out[11]);
        out[12] = fmaf(e, v3.x, out[12]); out[13] = fmaf(e, v3.y, out[13]);
        out[14] = fmaf(e, v3.z, out[14]); out[15] = fmaf(e, v3.w, out[15]);
    }
    float rinv = 1.0f / sum;

    uint32_t* op = g_ao + ((size_t)(win << 6) + row) * CC + (h << 5) + hb;
#pragma unroll
    for (int d = 0; d < 16; d += 4) {
        uint4 u;
        u.x = f2tf32(out[d] * rinv);     u.y = f2tf32(out[d + 1] * rinv);
        u.z = f2tf32(out[d + 2] * rinv); u.w = f2tf32(out[d + 3] * rinv);
        *reinterpret_cast<uint4*>(op + d) = u;
    }
}

// ---------------------------------------------------------------------------
// Projection GEMM (tf32, cp.async 3-stage): M=131072, N=256, K=256; fused
// window-reverse + unshift scatter. grid = (4, 1024), block = 256.
// ---------------------------------------------------------------------------
__global__ __launch_bounds__(256) void proj_gemm_tc(
    const float* __restrict__ pb, float* __restrict__ out) {
    extern __shared__ uint32_t dyn[];
    const uint32_t smem_u32 = (uint32_t)__cvta_generic_to_shared(dyn);

    const int tid = threadIdx.x;
    const int mb  = blockIdx.y;
    const int jt  = blockIdx.x;

    const int lane  = tid & 31, warp = tid >> 5;
    const int warpM = warp & 3, warpN = warp >> 2;
    const int la_row = tid >> 1;
    const int la_seg = (tid & 1) << 4;
    const int lb_row = tid >> 2;
    const int lb_seg = (tid & 3) << 3;
    const uint32_t* aRow = g_ao + (size_t)((mb << 7) + la_row) * 256 + la_seg;
    const uint32_t* wRow = g_wp + ((jt << 6) + lb_row) * 256 + lb_seg;

    float acc[2][4][4] = {};

    auto issue = [&](int st) {
        int buf = st % 3;
        uint32_t A = smem_u32 + (buf * STAGE_WORDS) * 4;
        uint32_t Bb = A + A_WORDS * 4;
        int k0 = st << 5;
#pragma unroll
        for (int v = 0; v < 4; v++)
            cp16(A + (la_row * 36 + la_seg + v * 4) * 4, aRow + k0 + v * 4);
        cp16(Bb + (lb_row * 36 + lb_seg) * 4,     wRow + k0);
        cp16(Bb + (lb_row * 36 + lb_seg + 4) * 4, wRow + k0 + 4);
        cp_commit();
    };
    auto compute = [&](int buf) {
        const uint32_t* A = dyn + buf * STAGE_WORDS;
        const uint32_t* B = A + A_WORDS;
#pragma unroll
        for (int ksb = 0; ksb < 4; ksb++) {
            uint32_t a[2][4], b[4][2];
            const int kc = (ksb << 3) + (lane & 3);
#pragma unroll
            for (int mf = 0; mf < 2; mf++) {
                int r = (warpM << 5) + (mf << 4) + (lane >> 2);
                a[mf][0] = A[r * 36 + kc];       a[mf][1] = A[(r + 8) * 36 + kc];
                a[mf][2] = A[r * 36 + kc + 4];   a[mf][3] = A[(r + 8) * 36 + kc + 4];
            }
#pragma unroll
            for (int nf = 0; nf < 4; nf++) {
                int n = (warpN << 5) + (nf << 3) + (lane >> 2);
                b[nf][0] = B[n * 36 + kc];
                b[nf][1] = B[n * 36 + kc + 4];
            }
#pragma unroll
            for (int mf = 0; mf < 2; mf++)
#pragma unroll
                for (int nf = 0; nf < 4; nf++)
                    mma_tf32(acc[mf][nf], a[mf], b[nf], acc[mf][nf]);
        }
    };

    issue(0);
    issue(1);
#pragma unroll
    for (int it = 0; it < 8; it++) {
        if (it < 7) asm volatile("cp.async.wait_group 1;" ::: "memory");
        else        asm volatile("cp.async.wait_group 0;" ::: "memory");
        __syncthreads();
        if (it < 6) issue(it + 2);
        compute(it % 3);
    }

#pragma unroll
    for (int nf = 0; nf < 4; nf++) {
        int jg = (jt << 6) + (warpN << 5) + (nf << 3) + ((lane & 3) << 1);
        float2 bias = make_float2(pb[jg], pb[jg + 1]);
#pragma unroll
        for (int mf = 0; mf < 2; mf++) {
#pragma unroll
            for (int half = 0; half < 2; half++) {
                int r  = (warpM << 5) + (mf << 4) + (lane >> 2) + half * 8;
                int gm = (mb << 7) + r;
                int win = gm >> 6, n = gm & 63;
                int b = win >> 8, wloc = win & 255, wy = wloc >> 4, wx = wloc & 15;
                int ly = n >> 3, lx = n & 7;
                int hd_ = ((wy << 3) + ly + SH) & 127;
                int wd_ = ((wx << 3) + lx + SH) & 127;
                size_t rowoff = ((size_t)((((b << 7) + hd_) << 7) | wd_)) << 8;
                float2 val = make_float2(acc[mf][nf][half * 2 + 0] + bias.x,
                                         acc[mf][nf][half * 2 + 1] + bias.y);
                *reinterpret_cast<float2*>(out + rowoff + jg) = val;
            }
        }
    }
}

// ---------------------------------------------------------------------------
extern "C" void kernel_launch(void* const* d_in, const int* in_sizes, int n_in,
                              void* d_out, int out_size) {
    const float* x      = (const float*)d_in[0];
    const float* qkv_w  = (const float*)d_in[1];
    const float* q_bias = (const float*)d_in[2];
    const float* v_bias = (const float*)d_in[3];
    const float* lscale = (const float*)d_in[4];
    const float* cpb_w1 = (const float*)d_in[5];
    const float* cpb_b1 = (const float*)d_in[6];
    const float* cpb_w2 = (const float*)d_in[7];
    const float* proj_w = (const float*)d_in[8];
    const float* proj_b = (const float*)d_in[9];
    float* out = (float*)d_out;

    cudaFuncSetAttribute(qkv_gemm_tc, cudaFuncAttributeMaxDynamicSharedMemorySize,
                         QKV_SMEM_BYTES);
    cudaFuncSetAttribute(proj_gemm_tc, cudaFuncAttributeMaxDynamicSharedMemorySize,
                         PROJ_SMEM_BYTES);

    uint32_t* xt_dev;  cudaGetSymbolAddress((void**)&xt_dev, g_xt);
    uint32_t* wq_dev;  cudaGetSymbolAddress((void**)&wq_dev, g_wq);
    uint32_t* wp_dev;  cudaGetSymbolAddress((void**)&wp_dev, g_wp);

    // pre-convert operands to tf32 bits
    conv_tf32<<<32768, 256>>>((const float4*)x, (uint4*)xt_dev, 8 * 16384 * 256 / 4);
    conv_tf32<<<192, 256>>>((const float4*)qkv_w, (uint4*)wq_dev, 768 * 256 / 4);
    conv_tf32<<<64, 256>>>((const float4*)proj_w, (uint4*)wp_dev, 256 * 256 / 4);

    cpb_stage1<<<8, 256>>>(cpb_w1, cpb_b1, cpb_w2);
    cpb_stage2<<<128, 256>>>();
    qkv_gemm_tc<<<dim3(12, 1024), 256, QKV_SMEM_BYTES>>>(q_bias, v_bias);
    attn_kernel<<<16384, 128>>>(lscale);
    proj_gemm_tc<<<dim3(4, 1024), 256, PROJ_SMEM_BYTES>>>(proj_b, out);
}

// round 13
// speedup vs baseline: 1.0023x; 1.0005x over previous
#include <cuda_runtime.h>
#include <cstdint>

// ---------------------------------------------------------------------------
// ShiftWindowMSA (Swin-V2): B=8, H=W=128, C=256, heads=8, hd=32, ws=8, ss=4
// Round 8: pre-converted tf32 operands + cp.async 3-stage GEMM pipelines,
// attention with 2 threads/query-row (shfl-combined dots) for occupancy.
// ---------------------------------------------------------------------------

constexpr int CC    = 256;
constexpr int HEADS = 8;
constexpr int HD    = 32;
constexpr int SH    = 4;
constexpr int NTOK  = 64;
constexpr int BWIN  = 2048;

constexpr int A_WORDS = 128 * 36;              // 4608
constexpr int B_WORDS = 64 * 36;               // 2304
constexpr int STAGE_WORDS = A_WORDS + B_WORDS; // 6912
constexpr int QKV_SMEM_BYTES  = (3 * STAGE_WORDS + 128) * 4;  // + rowOff
constexpr int PROJ_SMEM_BYTES = (3 * STAGE_WORDS) * 4;

__device__ float    g_q[BWIN * HEADS * NTOK * HD];
__device__ float    g_k[BWIN * HEADS * NTOK * HD];
__device__ float    g_v[BWIN * HEADS * NTOK * HD];
__device__ uint32_t g_ao[BWIN * NTOK * CC];      // tf32 bits
__device__ uint32_t g_xt[8 * 16384 * 256];       // x as tf32 bits
__device__ uint32_t g_wq[768 * 256];             // qkv_w as tf32 bits
__device__ uint32_t g_wp[256 * 256];             // proj_w as tf32 bits
__device__ float    g_bt[225 * 8];
__device__ float    g_bias[HEADS * NTOK * NTOK]; // [h][m(key)][n(query)]

// ---------------------------------------------------------------------------
__device__ __forceinline__ uint32_t f2tf32(float f) {
    uint32_t r;
    asm("cvt.rna.tf32.f32 %0, %1;" : "=r"(r) : "f"(f));
    return r;
}
__device__ __forceinline__ uint4 cvt4(float4 f) {
    uint4 u;
    u.x = f2tf32(f.x); u.y = f2tf32(f.y); u.z = f2tf32(f.z); u.w = f2tf32(f.w);
    return u;
}
__device__ __forceinline__ void mma_tf32(float* d, const uint32_t* a,
                                         const uint32_t* b, const float* c) {
    asm("mma.sync.aligned.m16n8k8.row.col.f32.tf32.tf32.f32 "
        "{%0,%1,%2,%3}, {%4,%5,%6,%7}, {%8,%9}, {%10,%11,%12,%13};"
        : "=f"(d[0]), "=f"(d[1]), "=f"(d[2]), "=f"(d[3])
        : "r"(a[0]), "r"(a[1]), "r"(a[2]), "r"(a[3]),
          "r"(b[0]), "r"(b[1]),
          "f"(c[0]), "f"(c[1]), "f"(c[2]), "f"(c[3]));
}
__device__ __forceinline__ void cp16(uint32_t s, const void* g) {
    asm volatile("cp.async.cg.shared.global [%0], [%1], 16;" :: "r"(s), "l"(g));
}
__device__ __forceinline__ void cp_commit() {
    asm volatile("cp.async.commit_group;" ::: "memory");
}

// ---------------------------------------------------------------------------
// tf32 pre-conversion
// ---------------------------------------------------------------------------
__global__ void conv_tf32(const float4* __restrict__ s, uint4* __restrict__ d, int n4) {
    int i = blockIdx.x * blockDim.x + threadIdx.x;
    if (i < n4) d[i] = cvt4(s[i]);
}

// ---------------------------------------------------------------------------
// CPB MLP
// ---------------------------------------------------------------------------
__device__ __forceinline__ float cpb_coord(int i) {
    float c = (float)(i - 7) * (8.0f / 7.0f);
    float a = log2f(fabsf(c) + 1.0f) * (1.0f / 3.0f);
    return (c < 0.0f) ? -a : a;
}

__global__ void cpb_stage1(const float* __restrict__ w1, const float* __restrict__ b1,
                           const float* __restrict__ w2) {
    int idx = blockIdx.x * blockDim.x + threadIdx.x;
    if (idx >= 225 * 8) return;
    int t = idx >> 3, h = idx & 7;
    float t0 = cpb_coord(t / 15);
    float t1 = cpb_coord(t % 15);
    const float* w2h = w2 + h * 512;
    float acc = 0.0f;
    for (int o = 0; o < 512; o++) {
        float hid = fmaxf(fmaf(t0, w1[2 * o], fmaf(t1, w1[2 * o + 1], b1[o])), 0.0f);
        acc = fmaf(hid, w2h[o], acc);
    }
    g_bt[idx] = acc;
}

__global__ void cpb_stage2() {
    int idx = blockIdx.x * blockDim.x + threadIdx.x;
    int h = idx >> 12, rest = idx & 4095, m = rest >> 6, n = rest & 63;
    int dy = (n >> 3) - (m >> 3) + 7;
    int dx = (n & 7) - (m & 7) + 7;
    float b = g_bt[(dy * 15 + dx) * 8 + h];
    g_bias[idx] = 16.0f / (1.0f + __expf(-b));
}

// ---------------------------------------------------------------------------
// QKV GEMM (tf32, cp.async 3-stage): M=131072 gathered, N=768, K=256.
// 128x64 tile, BK=32. grid = (12, 1024), block = 256.
// ---------------------------------------------------------------------------
__global__ __launch_bounds__(256) void qkv_gemm_tc(
    const float* __restrict__ qb, const float* __restrict__ vb) {
    extern __shared__ uint32_t dyn[];
    int* rowOff = (int*)(dyn + 3 * STAGE_WORDS);
    const uint32_t smem_u32 = (uint32_t)__cvta_generic_to_shared(dyn);

    const int tid = threadIdx.x;
    const int mb  = blockIdx.y;
    const int jt  = blockIdx.x;

    if (tid < 128) {
        int gm = (mb << 7) + tid;
        int win = gm >> 6, n = gm & 63;
        int b = win >> 8, wloc = win & 255, wy = wloc >> 4, wx = wloc & 15;
        int ly = n >> 3, lx = n & 7;
        int hs  = ((wy << 3) + ly + SH) & 127;
        int ws_ = ((wx << 3) + lx + SH) & 127;
        rowOff[tid] = ((((b << 7) + hs) << 7) | ws_) << 8;
    }
    __syncthreads();

    const int lane  = tid & 31, warp = tid >> 5;
    const int warpM = warp & 3, warpN = warp >> 2;
    const int la_row = tid >> 1;           // 0..127
    const int la_seg = (tid & 1) << 4;     // 0 / 16
    const int lb_row = tid >> 2;           // 0..63 (n)
    const int lb_seg = (tid & 3) << 3;     // 0,8,16,24 (k)
    const uint32_t* xRow = g_xt + rowOff[la_row] + la_seg;
    const uint32_t* wRow = g_wq + ((jt << 6) + lb_row) * 256 + lb_seg;

    float acc[2][4][4] = {};

    auto issue = [&](int st) {
        int buf = st % 3;
        uint32_t A = smem_u32 + (buf * STAGE_WORDS) * 4;
        uint32_t Bb = A + A_WORDS * 4;
        int k0 = st << 5;
#pragma unroll
        for (int v = 0; v < 4; v++)
            cp16(A + (la_row * 36 + la_seg + v * 4) * 4, xRow + k0 + v * 4);
        cp16(Bb + (lb_row * 36 + lb_seg) * 4,     wRow + k0);
        cp16(Bb + (lb_row * 36 + lb_seg + 4) * 4, wRow + k0 + 4);
        cp_commit();
    };
    auto compute = [&](int buf) {
        const uint32_t* A = dyn + buf * STAGE_WORDS;
        const uint32_t* B = A + A_WORDS;
#pragma unroll
        for (int ksb = 0; ksb < 4; ksb++) {
            uint32_t a[2][4], b[4][2];
            const int kc = (ksb << 3) + (lane & 3);
#pragma unroll
            for (int mf = 0; mf < 2; mf++) {
                int r = (warpM << 5) + (mf << 4) + (lane >> 2);
                a[mf][0] = A[r * 36 + kc];       a[mf][1] = A[(r + 8) * 36 + kc];
                a[mf][2] = A[r * 36 + kc + 4];   a[mf][3] = A[(r + 8) * 36 + kc + 4];
            }
#pragma unroll
            for (int nf = 0; nf < 4; nf++) {
                int n = (warpN << 5) + (nf << 3) + (lane >> 2);
                b[nf][0] = B[n * 36 + kc];
                b[nf][1] = B[n * 36 + kc + 4];
            }
#pragma unroll
            for (int mf = 0; mf < 2; mf++)
#pragma unroll
                for (int nf = 0; nf < 4; nf++)
                    mma_tf32(acc[mf][nf], a[mf], b[nf], acc[mf][nf]);
        }
    };

    issue(0);
    issue(1);
#pragma unroll
    for (int it = 0; it < 8; it++) {
        if (it < 7) asm volatile("cp.async.wait_group 1;" ::: "memory");
        else        asm volatile("cp.async.wait_group 0;" ::: "memory");
        __syncthreads();
        if (it < 6) issue(it + 2);
        compute(it % 3);
    }

    const int sel = jt >> 2;   // 0:q 1:k 2:v
    float* dstBase = (sel == 0) ? g_q : ((sel == 1) ? g_k : g_v);
#pragma unroll
    for (int nf = 0; nf < 4; nf++) {
        int jg = (jt << 6) + (warpN << 5) + (nf << 3) + ((lane & 3) << 1);
        float2 bias = make_float2(0.0f, 0.0f);
        if (sel == 0)      bias = make_float2(qb[jg], qb[jg + 1]);
        else if (sel == 2) bias = make_float2(vb[jg - 512], vb[jg - 511]);
        int head = (jg >> 5) & 7, d = jg & 31;
#pragma unroll
        for (int mf = 0; mf < 2; mf++) {
#pragma unroll
            for (int half = 0; half < 2; half++) {
                int r  = (warpM << 5) + (mf << 4) + (lane >> 2) + half * 8;
                int gm = (mb << 7) + r;
                int win = gm >> 6, n = gm & 63;
                float2 val = make_float2(acc[mf][nf][half * 2 + 0] + bias.x,
                                         acc[mf][nf][half * 2 + 1] + bias.y);
                float* dst = dstBase + ((size_t)(((win << 3) + head) << 6 | n) << 5) + d;
                *reinterpret_cast<float2*>(dst) = val;
            }
        }
    }
}

// ---------------------------------------------------------------------------
// Attention: one (win,head) pair per 128-thread block; 2 threads per query
// row (d-halves combined via shfl_xor(1)). K+V in smem (18.4 KB), single-pass
// softmax (mx = scale+16 bound), bitmask shift mask, tf32 output into g_ao.
// grid = 16384, block = 128.
// ---------------------------------------------------------------------------
__device__ __forceinline__ int region9(int wy, int wx, int n) {
    int rh = (wy == 15) ? (((n >> 3) < 4) ? 1 : 2) : 0;
    int rw = (wx == 15) ? (((n & 7) < 4) ? 1 : 2) : 0;
    return rh * 3 + rw;
}

__global__ __launch_bounds__(128) void attn_kernel(const float* __restrict__ ls) {
    __shared__ float ks[64][36];
    __shared__ float vs[64][36];
    const int tid  = threadIdx.x;
    const int row  = tid >> 1;       // query / K row 0..63
    const int hb   = (tid & 1) << 4; // d-half base: 0 or 16
    const int pair = blockIdx.x;
    const int win  = pair >> 3, h = pair & 7;

    // stage K and V
    {
        const float4* kp = reinterpret_cast<const float4*>(
            g_k + (size_t)pair * (NTOK * HD));
        const float4* vp = reinterpret_cast<const float4*>(
            g_v + (size_t)pair * (NTOK * HD));
#pragma unroll
        for (int i = tid; i < NTOK * HD / 4; i += 128) {
            *reinterpret_cast<float4*>(&ks[i >> 3][(i & 7) << 2]) = kp[i];
            *reinterpret_cast<float4*>(&vs[i >> 3][(i & 7) << 2]) = vp[i];
        }
    }
    __syncthreads();

    // normalize own K row-half (combine norms across the 2 half-threads)
    {
        float4 k0 = *reinterpret_cast<float4*>(&ks[row][hb]);
        float4 k1 = *reinterpret_cast<float4*>(&ks[row][hb + 4]);
        float4 k2 = *reinterpret_cast<float4*>(&ks[row][hb + 8]);
        float4 k3 = *reinterpret_cast<float4*>(&ks[row][hb + 12]);
        float s0 = fmaf(k0.x, k0.x, fmaf(k0.y, k0.y, fmaf(k0.z, k0.z, k0.w * k0.w)));
        float s1 = fmaf(k1.x, k1.x, fmaf(k1.y, k1.y, fmaf(k1.z, k1.z, k1.w * k1.w)));
        float s2 = fmaf(k2.x, k2.x, fmaf(k2.y, k2.y, fmaf(k2.z, k2.z, k2.w * k2.w)));
        float s3 = fmaf(k3.x, k3.x, fmaf(k3.y, k3.y, fmaf(k3.z, k3.z, k3.w * k3.w)));
        float s = (s0 + s1) + (s2 + s3);
        s += __shfl_xor_sync(0xffffffffu, s, 1);
        float inv = rsqrtf(fmaxf(s, 1e-24f));
        k0.x *= inv; k0.y *= inv; k0.z *= inv; k0.w *= inv;
        k1.x *= inv; k1.y *= inv; k1.z *= inv; k1.w *= inv;
        k2.x *= inv; k2.y *= inv; k2.z *= inv; k2.w *= inv;
        k3.x *= inv; k3.y *= inv; k3.z *= inv; k3.w *= inv;
        *reinterpret_cast<float4*>(&ks[row][hb])      = k0;
        *reinterpret_cast<float4*>(&ks[row][hb + 4])  = k1;
        *reinterpret_cast<float4*>(&ks[row][hb + 8])  = k2;
        *reinterpret_cast<float4*>(&ks[row][hb + 12]) = k3;
    }

    // own Q row-half, normalized and pre-scaled
    float q[16];
    float scale = __expf(fminf(ls[h], 4.6051702f));
    {
        const float4* qp = reinterpret_cast<const float4*>(
            g_q + ((size_t)pair * NTOK + row) * HD + hb);
        float s0 = 0.0f, s1 = 0.0f, s2 = 0.0f, s3 = 0.0f;
#pragma unroll
        for (int d4 = 0; d4 < 4; d4++) {
            float4 f = qp[d4];
            q[d4 * 4 + 0] = f.x; q[d4 * 4 + 1] = f.y;
            q[d4 * 4 + 2] = f.z; q[d4 * 4 + 3] = f.w;
            s0 = fmaf(f.x, f.x, s0); s1 = fmaf(f.y, f.y, s1);
            s2 = fmaf(f.z, f.z, s2); s3 = fmaf(f.w, f.w, s3);
        }
        float s = (s0 + s1) + (s2 + s3);
        s += __shfl_xor_sync(0xffffffffu, s, 1);
        float inv = rsqrtf(fmaxf(s, 1e-24f)) * scale;
#pragma unroll
        for (int d = 0; d < 16; d++) q[d] *= inv;
    }
    __syncthreads();

    // shift mask bitmask (nonzero only for boundary windows)
    const int wloc = win & 255, wy = wloc >> 4, wx = wloc & 15;
    uint32_t mlo = 0, mhi = 0;
    if (wy == 15 || wx == 15) {
        const int rn = region9(wy, wx, row);
        for (int m = 0; m < 64; m++)
            if (region9(wy, wx, m) != rn) {
                if (m < 32) mlo |= (1u << m); else mhi |= (1u << (m - 32));
            }
    }

    const float* biasT = g_bias + (h << 12) + row;   // [h][m][n]: +64 per m
    const float mx = scale + 16.0f;

    float sum = 0.0f;
    float out[16] = {};
#pragma unroll 4
    for (int m = 0; m < 64; m++) {
        float4 k0 = *reinterpret_cast<const float4*>(&ks[m][hb]);
        float4 k1 = *reinterpret_cast<const float4*>(&ks[m][hb + 4]);
        float4 k2 = *reinterpret_cast<const float4*>(&ks[m][hb + 8]);
        float4 k3 = *reinterpret_cast<const float4*>(&ks[m][hb + 12]);
        float a0 = fmaf(q[0], k0.x, fmaf(q[4],  k1.x, fmaf(q[8],  k2.x, q[12] * k3.x)));
        float a1 = fmaf(q[1], k0.y, fmaf(q[5],  k1.y, fmaf(q[9],  k2.y, q[13] * k3.y)));
        float a2 = fmaf(q[2], k0.z, fmaf(q[6],  k1.z, fmaf(q[10], k2.z, q[14] * k3.z)));
        float a3 = fmaf(q[3], k0.w, fmaf(q[7],  k1.w, fmaf(q[11], k2.w, q[15] * k3.w)));
        float half_dot = (a0 + a1) + (a2 + a3);
        float dot = half_dot + __shfl_xor_sync(0xffffffffu, half_dot, 1);
        uint32_t bit = (m < 32) ? ((mlo >> m) & 1u) : ((mhi >> (m - 32)) & 1u);
        float v = dot + __ldg(&biasT[m << 6]) + (bit ? -100.0f : 0.0f);
        float e = __expf(v - mx);
        sum += e;
        float4 v0 = *reinterpret_cast<const float4*>(&vs[m][hb]);
        float4 v1 = *reinterpret_cast<const float4*>(&vs[m][hb + 4]);
        float4 v2 = *reinterpret_cast<const float4*>(&vs[m][hb + 8]);
        float4 v3 = *reinterpret_cast<const float4*>(&vs[m][hb + 12]);
        out[0]  = fmaf(e, v0.x, out[0]);  out[1]  = fmaf(e, v0.y, out[1]);
        out[2]  = fmaf(e, v0.z, out[2]);  out[3]  = fmaf(e, v0.w, out[3]);
        out[4]  = fmaf(e, v1.x, out[4]);  out[5]  = fmaf(e, v1.y, out[5]);
        out[6]  = fmaf(e, v1.z, out[6]);  out[7]  = fmaf(e, v1.w, out[7]);
        out[8]  = fmaf(e, v2.x, out[8]);  out[9]  = fmaf(e, v2.y, out[9]);
        out[10] = fmaf(e, v2.z, out[10]); out[11] = fmaf(e, v2.w, out[11]);
        out[12] = fmaf(e, v3.x, out[12]); out[13] = fmaf(e, v3.y, out[13]);
        out[14] = fmaf(e, v3.z, out[14]); out[15] = fmaf(e, v3.w, out[15]);
    }
    float rinv = 1.0f / sum;

    uint32_t* op = g_ao + ((size_t)(win << 6) + row) * CC + (h << 5) + hb;
#pragma unroll
    for (int d = 0; d < 16; d += 4) {
        uint4 u;
        u.x = f2tf32(out[d] * rinv);     u.y = f2tf32(out[d + 1] * rinv);
        u.z = f2tf32(out[d + 2] * rinv); u.w = f2tf32(out[d + 3] * rinv);
        *reinterpret_cast<uint4*>(op + d) = u;
    }
}

// ---------------------------------------------------------------------------
// Projection GEMM (tf32, cp.async 3-stage): M=131072, N=256, K=256; fused
// window-reverse + unshift scatter. grid = (4, 1024), block = 256.
// ---------------------------------------------------------------------------
__global__ __launch_bounds__(256) void proj_gemm_tc(
    const float* __restrict__ pb, float* __restrict__ out) {
    extern __shared__ uint32_t dyn[];
    const uint32_t smem_u32 = (uint32_t)__cvta_generic_to_shared(dyn);

    const int tid = threadIdx.x;
    const int mb  = blockIdx.y;
    const int jt  = blockIdx.x;

    const int lane  = tid & 31, warp = tid >> 5;
    const int warpM = warp & 3, warpN = warp >> 2;
    const int la_row = tid >> 1;
    const int la_seg = (tid & 1) << 4;
    const int lb_row = tid >> 2;
    const int lb_seg = (tid & 3) << 3;
    const uint32_t* aRow = g_ao + (size_t)((mb << 7) + la_row) * 256 + la_seg;
    const uint32_t* wRow = g_wp + ((jt << 6) + lb_row) * 256 + lb_seg;

    float acc[2][4][4] = {};

    auto issue = [&](int st) {
        int buf = st % 3;
        uint32_t A = smem_u32 + (buf * STAGE_WORDS) * 4;
        uint32_t Bb = A + A_WORDS * 4;
        int k0 = st << 5;
#pragma unroll
        for (int v = 0; v < 4; v++)
            cp16(A + (la_row * 36 + la_seg + v * 4) * 4, aRow + k0 + v * 4);
        cp16(Bb + (lb_row * 36 + lb_seg) * 4,     wRow + k0);
        cp16(Bb + (lb_row * 36 + lb_seg + 4) * 4, wRow + k0 + 4);
        cp_commit();
    };
    auto compute = [&](int buf) {
        const uint32_t* A = dyn + buf * STAGE_WORDS;
        const uint32_t* B = A + A_WORDS;
#pragma unroll
        for (int ksb = 0; ksb < 4; ksb++) {
            uint32_t a[2][4], b[4][2];
            const int kc = (ksb << 3) + (lane & 3);
#pragma unroll
            for (int mf = 0; mf < 2; mf++) {
                int r = (warpM << 5) + (mf << 4) + (lane >> 2);
                a[mf][0] = A[r * 36 + kc];       a[mf][1] = A[(r + 8) * 36 + kc];
                a[mf][2] = A[r * 36 + kc + 4];   a[mf][3] = A[(r + 8) * 36 + kc + 4];
            }
#pragma unroll
            for (int nf = 0; nf < 4; nf++) {
                int n = (warpN << 5) + (nf << 3) + (lane >> 2);
                b[nf][0] = B[n * 36 + kc];
                b[nf][1] = B[n * 36 + kc + 4];
            }
#pragma unroll
            for (int mf = 0; mf < 2; mf++)
#pragma unroll
                for (int nf = 0; nf < 4; nf++)
                    mma_tf32(acc[mf][nf], a[mf], b[nf], acc[mf][nf]);
        }
    };

    issue(0);
    issue(1);
#pragma unroll
    for (int it = 0; it < 8; it++) {
        if (it < 7) asm volatile("cp.async.wait_group 1;" ::: "memory");
        else        asm volatile("cp.async.wait_group 0;" ::: "memory");
        __syncthreads();
        if (it < 6) issue(it + 2);
        compute(it % 3);
    }

#pragma unroll
    for (int nf = 0; nf < 4; nf++) {
        int jg = (jt << 6) + (warpN << 5) + (nf << 3) + ((lane & 3) << 1);
        float2 bias = make_float2(pb[jg], pb[jg + 1]);
#pragma unroll
        for (int mf = 0; mf < 2; mf++) {
#pragma unroll
            for (int half = 0; half < 2; half++) {
                int r  = (warpM << 5) + (mf << 4) + (lane >> 2) + half * 8;
                int gm = (mb << 7) + r;
                int win = gm >> 6, n = gm & 63;
                int b = win >> 8, wloc = win & 255, wy = wloc >> 4, wx = wloc & 15;
                int ly = n >> 3, lx = n & 7;
                int hd_ = ((wy << 3) + ly + SH) & 127;
                int wd_ = ((wx << 3) + lx + SH) & 127;
                size_t rowoff = ((size_t)((((b << 7) + hd_) << 7) | wd_)) << 8;
                float2 val = make_float2(acc[mf][nf][half * 2 + 0] + bias.x,
                                         acc[mf][nf][half * 2 + 1] + bias.y);
                *reinterpret_cast<float2*>(out + rowoff + jg) = val;
            }
        }
    }
}

// ---------------------------------------------------------------------------
extern "C" void kernel_launch(void* const* d_in, const int* in_sizes, int n_in,
                              void* d_out, int out_size) {
    const float* x      = (const float*)d_in[0];
    const float* qkv_w  = (const float*)d_in[1];
    const float* q_bias = (const float*)d_in[2];
    const float* v_bias = (const float*)d_in[3];
    const float* lscale = (const float*)d_in[4];
    const float* cpb_w1 = (const float*)d_in[5];
    const float* cpb_b1 = (const float*)d_in[6];
    const float* cpb_w2 = (const float*)d_in[7];
    const float* proj_w = (const float*)d_in[8];
    const float* proj_b = (const float*)d_in[9];
    float* out = (float*)d_out;

    cudaFuncSetAttribute(qkv_gemm_tc, cudaFuncAttributeMaxDynamicSharedMemorySize,
                         QKV_SMEM_BYTES);
    cudaFuncSetAttribute(proj_gemm_tc, cudaFuncAttributeMaxDynamicSharedMemorySize,
                         PROJ_SMEM_BYTES);

    uint32_t* xt_dev;  cudaGetSymbolAddress((void**)&xt_dev, g_xt);
    uint32_t* wq_dev;  cudaGetSymbolAddress((void**)&wq_dev, g_wq);
    uint32_t* wp_dev;  cudaGetSymbolAddress((void**)&wp_dev, g_wp);

    // pre-convert operands to tf32 bits
    conv_tf32<<<32768, 256>>>((const float4*)x, (uint4*)xt_dev, 8 * 16384 * 256 / 4);
    conv_tf32<<<192, 256>>>((const float4*)qkv_w, (uint4*)wq_dev, 768 * 256 / 4);
    conv_tf32<<<64, 256>>>((const float4*)proj_w, (uint4*)wp_dev, 256 * 256 / 4);

    cpb_stage1<<<8, 256>>>(cpb_w1, cpb_b1, cpb_w2);
    cpb_stage2<<<128, 256>>>();
    qkv_gemm_tc<<<dim3(12, 1024), 256, QKV_SMEM_BYTES>>>(q_bias, v_bias);
    attn_kernel<<<16384, 128>>>(lscale);
    proj_gemm_tc<<<dim3(4, 1024), 256, PROJ_SMEM_BYTES>>>(proj_b, out);
}